// round 10
// baseline (speedup 1.0000x reference)
#include <cuda_runtime.h>

// EnergyGatedDeltaModel — GB300 sm_103a
// R9 = R8 arithmetic (bit-identical decisions/values) + latency-shadow speculation:
//  - while the slow-path 256-cyc NEON chain runs, compute BOTH candidate
//    next-step dots (keep = dot(M,k'), take = dot(Mn,k')) and the fast batch's
//    update+dot; select after the gate resolves (identical values, earlier).
//  - cache the folded eo scalar per batch (bit-identical to fold16(aold)).
//  - v is software-pipelined one step ahead in all paths.

#define B_ 512
#define L_ 2048
#define H_ 32
#define V_ 64
#define STEPS (L_ - 1)
#define THRESH 1.0f
#define ROWP 36

__device__ float g_table[V_ * H_];
__device__ float g_ksq[V_];
__device__ float g_denom[V_];
__device__ int   g_writes;

// NEON VF4xIC4 reduction of 32 products (R6-identical values).
__device__ __forceinline__ float neon_dot32(const float* x, const float* y) {
    float A[16];
#pragma unroll
    for (int c = 0; c < 16; c++) A[c] = __fmul_rn(x[c], y[c]);
#pragma unroll
    for (int c = 0; c < 16; c++) A[c] = fmaf(x[16 + c], y[16 + c], A[c]);
    float V[4];
#pragma unroll
    for (int l = 0; l < 4; l++)
        V[l] = __fadd_rn(__fadd_rn(__fadd_rn(A[l], A[4 + l]), A[8 + l]), A[12 + l]);
    return __fadd_rn(__fadd_rn(V[0], V[2]), __fadd_rn(V[1], V[3]));
}

__device__ __forceinline__ float neon_sum32(const float* t) {
    float A[16];
#pragma unroll
    for (int c = 0; c < 16; c++) A[c] = __fadd_rn(t[c], t[16 + c]);
    float V[4];
#pragma unroll
    for (int l = 0; l < 4; l++)
        V[l] = __fadd_rn(__fadd_rn(__fadd_rn(A[l], A[4 + l]), A[8 + l]), A[12 + l]);
    return __fadd_rn(__fadd_rn(V[0], V[2]), __fadd_rn(V[1], V[3]));
}

// ---------------------------------------------------------------------------
__global__ void precompute_kernel(const float* __restrict__ embed,
                                  const float* __restrict__ w1,
                                  const float* __restrict__ b1,
                                  const float* __restrict__ w2,
                                  const float* __restrict__ b2,
                                  const float* __restrict__ ln_g,
                                  const float* __restrict__ ln_b)
{
    __shared__ float h_sh[H_];
    __shared__ float s_sh[2 * H_];
    __shared__ float x_sh[H_];

    const int v = blockIdx.x;
    const int t = threadIdx.x;
    if (v == 0 && t == 0) g_writes = 0;

    if (t < H_) h_sh[t] = embed[v * H_ + t];
    __syncthreads();

    {
        const int j = t;
        float s = 0.0f;
#pragma unroll
        for (int i = 0; i < H_; i++) s = fmaf(h_sh[i], w1[i * 2 * H_ + j], s);
        s = __fadd_rn(s, b1[j]);
        s_sh[j] = fmaxf(s, 0.0f);
    }
    __syncthreads();

    if (t < H_) {
        const int i = t;
        float acc = 0.0f;
#pragma unroll
        for (int j = 0; j < 2 * H_; j++) acc = fmaf(s_sh[j], w2[j * H_ + i], acc);
        float ff = __fadd_rn(acc, b2[i]);
        x_sh[i] = __fadd_rn(h_sh[i], ff);
    }
    __syncthreads();

    if (t == 0) {
        float x[H_], d[H_], sq[H_];
#pragma unroll
        for (int i = 0; i < H_; i++) x[i] = x_sh[i];
        float mu = __fmul_rn(neon_sum32(x), 1.0f / H_);
#pragma unroll
        for (int i = 0; i < H_; i++) {
            d[i] = __fsub_rn(x[i], mu);
            sq[i] = __fmul_rn(d[i], d[i]);
        }
        float var = __fmul_rn(neon_sum32(sq), 1.0f / H_);
        float rs = __fdiv_rn(1.0f, __fsqrt_rn(__fadd_rn(var, 1e-5f)));
        float y[H_];
#pragma unroll
        for (int i = 0; i < H_; i++) {
            y[i] = __fadd_rn(__fmul_rn(__fmul_rn(d[i], rs), ln_g[i]), ln_b[i]);
            g_table[v * H_ + i] = y[i];
            sq[i] = __fmul_rn(y[i], y[i]);
        }
        float ksq = neon_sum32(sq);
        g_ksq[v]   = ksq;
        g_denom[v] = __fadd_rn(ksq, 1e-6f);
    }
}

// ---------------------------------------------------------------------------
// Slow-path primitives (values identical to R8).
// ---------------------------------------------------------------------------
__device__ __forceinline__ float chain64(const float* P, int c) {
    float a = 0.0f;
#pragma unroll
    for (int m = 0; m < 64; m++) {
        float s = P[(m >> 1) * ROWP + (m & 1) * 16 + c];
        a = fmaf(s, s, a);
    }
    return a;
}

__device__ __forceinline__ float fold16(float val, int base, unsigned FULL) {
    float V[4];
#pragma unroll
    for (int l = 0; l < 4; l++) {
        float a0 = __shfl_sync(FULL, val, base + l);
        float a1 = __shfl_sync(FULL, val, base + l + 4);
        float a2 = __shfl_sync(FULL, val, base + l + 8);
        float a3 = __shfl_sync(FULL, val, base + l + 12);
        V[l] = __fadd_rn(__fadd_rn(__fadd_rn(a0, a1), a2), a3);
    }
    return __fadd_rn(__fadd_rn(V[0], V[2]), __fadd_rn(V[1], V[3]));
}

__device__ __forceinline__ void store_row(float* buf, int lane, const float* Mrow) {
    float4* p = (float4*)(buf + lane * ROWP);
#pragma unroll
    for (int q = 0; q < 8; q++)
        p[q] = make_float4(Mrow[4*q], Mrow[4*q+1], Mrow[4*q+2], Mrow[4*q+3]);
}

// ---------------------------------------------------------------------------
__global__ void __launch_bounds__(32) scan_kernel(const int* __restrict__ seq,
                                                  const float* __restrict__ w_read,
                                                  const float* __restrict__ b_read,
                                                  const float* __restrict__ w_out,
                                                  const float* __restrict__ b_out,
                                                  float* __restrict__ out)
{
    __shared__ __align__(16) float tsh[V_ * H_];
    __shared__ __align__(16) float mnAb[H_ * ROWP];
    __shared__ __align__(16) float mnBb[H_ * ROWP];
    __shared__ __align__(16) float moAb[H_ * ROWP];
    __shared__ __align__(16) float moBb[H_ * ROWP];
    __shared__ float dnsh[V_];
    __shared__ float kssh[V_];
    __shared__ int   toksA[32];
    __shared__ int   toksB[32];
    __shared__ float scratch[H_];

    const int lane = threadIdx.x;
    const int bA   = blockIdx.x;
    const int bB   = blockIdx.x + 256;
    const unsigned FULL = 0xffffffffu;

    for (int i = lane; i < V_ * H_; i += 32) tsh[i] = g_table[i];
    dnsh[lane]      = g_denom[lane];
    dnsh[lane + 32] = g_denom[lane + 32];
    kssh[lane]      = g_ksq[lane];
    kssh[lane + 32] = g_ksq[lane + 32];
    __syncwarp();

    float MA[H_], MB[H_];
#pragma unroll
    for (int j = 0; j < H_; j++) { MA[j] = 0.0f; MB[j] = 0.0f; }

    float aoldA = 0.0f, aoldB = 0.0f;   // cached ||M||^2 chain accumulators (lanes<16)
    float eoA = 0.0f, eoB = 0.0f;       // cached fold16(aold) (warp-uniform)
    bool validA = true, validB = true;

    float vA = 0.0f, vB = 0.0f;         // pipelined dot(M, k_cur)
    int writes = 0;
    const int* sA = seq + bA * L_;
    const int* sB = seq + bB * L_;

    for (int t0 = 0; t0 < STEPS; t0 += 32) {
        toksA[lane] = sA[t0 + lane];
        toksB[lane] = sB[t0 + lane];
        __syncwarp();
        const int nfA = (t0 + 32 < L_) ? sA[t0 + 32] : 0;   // next chunk's first token
        const int nfB = (t0 + 32 < L_) ? sB[t0 + 32] : 0;
        const int tend = (STEPS - t0) < 32 ? (STEPS - t0) : 32;

        if (t0 == 0) {   // prologue dots (M=0 -> exactly 0, same expression)
            vA = neon_dot32(MA, tsh + toksA[0] * H_);
            vB = neon_dot32(MB, tsh + toksB[0] * H_);
        }

        for (int tt = 0; tt < tend; tt++) {
            const int tokA = toksA[tt];
            const int tokB = toksB[tt];
            const int tokAn = (tt + 1 < 32) ? toksA[tt + 1] : nfA;
            const int tokBn = (tt + 1 < 32) ? toksB[tt + 1] : nfB;
            const float* kA  = tsh + tokA * H_;
            const float* kB  = tsh + tokB * H_;
            const float* kAn = tsh + tokAn * H_;
            const float* kBn = tsh + tokBn * H_;
            const float dnA = dnsh[tokA], ksA = kssh[tokA];
            const float dnB = dnsh[tokB], ksB = kssh[tokB];

            const float uA = __fsub_rn(kA[lane], __fdiv_rn(vA, dnA));
            const float uB = __fsub_rn(kB[lane], __fdiv_rn(vB, dnB));

            float suvA = __fmul_rn(uA, vA);
            float suuA = __fmul_rn(uA, uA);
            float suvB = __fmul_rn(uB, vB);
            float suuB = __fmul_rn(uB, uB);
#pragma unroll
            for (int o = 16; o > 0; o >>= 1) {
                suvA += __shfl_xor_sync(FULL, suvA, o);
                suuA += __shfl_xor_sync(FULL, suuA, o);
                suvB += __shfl_xor_sync(FULL, suvB, o);
                suuB += __shfl_xor_sync(FULL, suuB, o);
            }
            const float dEA = __fadd_rn(__fadd_rn(suvA, suvA), __fmul_rn(suuA, ksA));
            const float dEB = __fadd_rn(__fadd_rn(suvB, suvB), __fmul_rn(suuB, ksB));

            const bool slowA = fabsf(dEA) < THRESH;
            const bool slowB = fabsf(dEB) < THRESH;
            int gateA = dEA > 0.0f;
            int gateB = dEB > 0.0f;

            if (!(slowA | slowB)) {
                if (gateA) {
                    writes++;
#pragma unroll
                    for (int j = 0; j < H_; j++) MA[j] = fmaf(uA, kA[j], MA[j]);
                    validA = false;
                }
                if (gateB) {
                    writes++;
#pragma unroll
                    for (int j = 0; j < H_; j++) MB[j] = fmaf(uB, kB[j], MB[j]);
                    validB = false;
                }
                vA = neon_dot32(MA, kAn);
                vB = neon_dot32(MB, kBn);
            } else {
                float MnA[H_], MnB[H_];
                if (slowA) {
#pragma unroll
                    for (int j = 0; j < H_; j++) MnA[j] = fmaf(uA, kA[j], MA[j]);
                    store_row(mnAb, lane, MnA);
                    if (!validA) store_row(moAb, lane, MA);
                } else if (gateA) {
                    writes++;
#pragma unroll
                    for (int j = 0; j < H_; j++) MA[j] = fmaf(uA, kA[j], MA[j]);
                    validA = false;
                }
                if (slowB) {
#pragma unroll
                    for (int j = 0; j < H_; j++) MnB[j] = fmaf(uB, kB[j], MB[j]);
                    store_row(mnBb, lane, MnB);
                    if (!validB) store_row(moBb, lane, MB);
                } else if (gateB) {
                    writes++;
#pragma unroll
                    for (int j = 0; j < H_; j++) MB[j] = fmaf(uB, kB[j], MB[j]);
                    validB = false;
                }
                __syncwarp();

                // speculative next-step dots (independent of the chains below;
                // the scheduler interleaves them into the chain latency shadow)
                float vAk, vAt = 0.0f, vBk, vBt = 0.0f;
                vAk = neon_dot32(MA, kAn);
                if (slowA) vAt = neon_dot32(MnA, kAn);
                vBk = neon_dot32(MB, kBn);
                if (slowB) vBt = neon_dot32(MnB, kBn);

                // chains + folds (R8-identical values; eo from cached scalars)
                if (slowA & slowB & validA & validB) {
                    float a = chain64((lane < 16) ? mnAb : mnBb, lane & 15);
                    float enA = fold16(a, 0, FULL);
                    float enB = fold16(a, 16, FULL);
                    gateA = enA > eoA;
                    gateB = enB > eoB;
                    float aB = __shfl_sync(FULL, a, (lane & 15) + 16);
                    if (gateA) { if (lane < 16) aoldA = a;  eoA = enA; }
                    if (gateB) { if (lane < 16) aoldB = aB; eoB = enB; }
                } else {
                    if (slowA) {
                        if (validA) {
                            float a = 0.0f;
                            if (lane < 16) a = chain64(mnAb, lane);
                            float en = fold16(a, 0, FULL);
                            gateA = en > eoA;
                            if (gateA) { if (lane < 16) aoldA = a; eoA = en; }
                        } else {
                            float a = chain64((lane < 16) ? moAb : mnAb, lane & 15);
                            float eoc = fold16(a, 0, FULL);
                            float en  = fold16(a, 16, FULL);
                            float an  = __shfl_sync(FULL, a, (lane & 15) + 16);
                            gateA = en > eoc;
                            if (lane < 16) aoldA = gateA ? an : a;
                            eoA = gateA ? en : eoc;
                            validA = true;
                        }
                    }
                    if (slowB) {
                        if (validB) {
                            float a = 0.0f;
                            if (lane < 16) a = chain64(mnBb, lane);
                            float en = fold16(a, 0, FULL);
                            gateB = en > eoB;
                            if (gateB) { if (lane < 16) aoldB = a; eoB = en; }
                        } else {
                            float a = chain64((lane < 16) ? moBb : mnBb, lane & 15);
                            float eoc = fold16(a, 0, FULL);
                            float en  = fold16(a, 16, FULL);
                            float an  = __shfl_sync(FULL, a, (lane & 15) + 16);
                            gateB = en > eoc;
                            if (lane < 16) aoldB = gateB ? an : a;
                            eoB = gateB ? en : eoc;
                            validB = true;
                        }
                    }
                }
                __syncwarp();

                // selection (values identical to post-gate computation)
                if (slowA) {
                    if (gateA) {
                        writes++;
#pragma unroll
                        for (int j = 0; j < H_; j++) MA[j] = MnA[j];
                    }
                    vA = gateA ? vAt : vAk;
                } else {
                    vA = vAk;
                }
                if (slowB) {
                    if (gateB) {
                        writes++;
#pragma unroll
                        for (int j = 0; j < H_; j++) MB[j] = MnB[j];
                    }
                    vB = gateB ? vBt : vBk;
                } else {
                    vB = vBk;
                }
            }
        }
        __syncwarp();
    }

    // -------- readout (both batches), identical arithmetic --------
#pragma unroll
    for (int pass = 0; pass < 2; pass++) {
        const int b = pass ? bB : bA;
        const float* M = pass ? MB : MA;
        const int qtok = (pass ? sB : sA)[L_ - 1];
        const float* qv = tsh + qtok * H_;
        float ctx = neon_dot32(M, qv);

        scratch[lane] = ctx;
        __syncwarp();
        float r = 0.0f;
#pragma unroll
        for (int j = 0; j < H_; j++) r = fmaf(scratch[j], w_read[j * H_ + lane], r);
        r = __fadd_rn(r, b_read[lane]);
        __syncwarp();
        scratch[lane] = r;
        __syncwarp();

        float o0 = 0.0f, o1 = 0.0f;
#pragma unroll
        for (int j = 0; j < H_; j++) {
            const float rj = scratch[j];
            o0 = fmaf(rj, w_out[j * V_ + lane], o0);
            o1 = fmaf(rj, w_out[j * V_ + lane + H_], o1);
        }
        out[b * V_ + lane]      = __fadd_rn(o0, b_out[lane]);
        out[b * V_ + lane + H_] = __fadd_rn(o1, b_out[lane + H_]);
        __syncwarp();
    }

    if (lane == 0) atomicAdd(&g_writes, writes);
}

// ---------------------------------------------------------------------------
__global__ void finalize_kernel(float* __restrict__ out, int out_size)
{
    if (out_size > B_ * V_)
        out[B_ * V_] = __fdiv_rn((float)g_writes, (float)(STEPS * B_));
}

extern "C" void kernel_launch(void* const* d_in, const int* in_sizes, int n_in,
                              void* d_out, int out_size)
{
    const int*   seq    = (const int*)d_in[0];
    const float* embed  = (const float*)d_in[1];
    const float* w1     = (const float*)d_in[2];
    const float* b1     = (const float*)d_in[3];
    const float* w2     = (const float*)d_in[4];
    const float* b2     = (const float*)d_in[5];
    const float* ln_g   = (const float*)d_in[6];
    const float* ln_b   = (const float*)d_in[7];
    const float* w_read = (const float*)d_in[8];
    const float* b_read = (const float*)d_in[9];
    const float* w_out  = (const float*)d_in[10];
    const float* b_out  = (const float*)d_in[11];
    float* out = (float*)d_out;

    precompute_kernel<<<V_, 64>>>(embed, w1, b1, w2, b2, ln_g, ln_b);
    scan_kernel<<<B_ / 2, 32>>>(seq, w_read, b_read, w_out, b_out, out);
    finalize_kernel<<<1, 1>>>(out, out_size);
}